// round 7
// baseline (speedup 1.0000x reference)
#include <cuda_runtime.h>
#include <math.h>

// Problem constants (fixed by reference)
#define VOCAB 100000
#define DIM   128
#define BATCH 16384
#define CTX   10
#define NEG   5

#define WARPS_PER_BLOCK 8
#define THREADS (WARPS_PER_BLOCK * 32)
#define ELEMS_PER_WARP 2
#define NUM_BLOCKS (BATCH / (WARPS_PER_BLOCK * ELEMS_PER_WARP))   // 1024: single CTA wave

// Scratch (no cudaMalloc allowed)
__device__ double       g_accum  = 0.0;
__device__ unsigned int g_ticket = 0;

__device__ __forceinline__ float log_sigmoid(float x) {
    // stable: min(x,0) - log1p(exp(-|x|))
    return fminf(x, 0.0f) - log1pf(expf(-fabsf(x)));
}

// Asymmetric L2 policy: pin u-table (larger unique miss stream), stream w-table.
__device__ __forceinline__ unsigned long long make_policy_keep() {
    unsigned long long pol;
    asm("createpolicy.fractional.L2::evict_last.b64 %0, 1.0;" : "=l"(pol));
    return pol;
}
__device__ __forceinline__ unsigned long long make_policy_stream() {
    unsigned long long pol;
    asm("createpolicy.fractional.L2::evict_first.b64 %0, 1.0;" : "=l"(pol));
    return pol;
}
__device__ __forceinline__ float4 ldg_pol(const float4* p, unsigned long long pol) {
    float4 v;
    asm("ld.global.nc.L2::cache_hint.v4.f32 {%0,%1,%2,%3}, [%4], %5;"
        : "=f"(v.x), "=f"(v.y), "=f"(v.z), "=f"(v.w)
        : "l"(p), "l"(pol));
    return v;
}

__global__ __launch_bounds__(THREADS)
void cbow_loss_fused(const int* __restrict__ pos_u,   // [B, CTX]
                     const int* __restrict__ pos_w,   // [B]
                     const int* __restrict__ neg_w,   // [B, NEG]
                     const float4* __restrict__ u_w,  // [VOCAB, 32] as float4
                     const float4* __restrict__ w_w,  // [VOCAB, 32] as float4
                     float* __restrict__ out)
{
    const int warp = threadIdx.x >> 5;
    const int lane = threadIdx.x & 31;
    const int b0 = (blockIdx.x * WARPS_PER_BLOCK + warp) * ELEMS_PER_WARP;
    const int b1 = b0 + 1;

    const unsigned long long pol_keep   = make_policy_keep();
    const unsigned long long pol_stream = make_policy_stream();

    // --- dual-chain gather-sum of context embeddings (2 batch elems lockstep) ---
    float4 usum0 = make_float4(0.f, 0.f, 0.f, 0.f);
    float4 usum1 = make_float4(0.f, 0.f, 0.f, 0.f);
    const int* pu0 = pos_u + b0 * CTX;
    const int* pu1 = pos_u + b1 * CTX;
    #pragma unroll
    for (int c = 0; c < CTX; ++c) {
        int i0 = __ldg(pu0 + c);
        int i1 = __ldg(pu1 + c);
        float4 v0 = ldg_pol(u_w + (size_t)i0 * 32 + lane, pol_keep);
        float4 v1 = ldg_pol(u_w + (size_t)i1 * 32 + lane, pol_keep);
        usum0.x += v0.x; usum0.y += v0.y; usum0.z += v0.z; usum0.w += v0.w;
        usum1.x += v1.x; usum1.y += v1.y; usum1.z += v1.z; usum1.w += v1.w;
    }

    // --- positive target rows (w-table: stream) ---
    int p0 = __ldg(pos_w + b0);
    int p1 = __ldg(pos_w + b1);
    float4 pr0 = ldg_pol(w_w + (size_t)p0 * 32 + lane, pol_stream);
    float4 pr1 = ldg_pol(w_w + (size_t)p1 * 32 + lane, pol_stream);
    float pd0 = usum0.x * pr0.x + usum0.y * pr0.y + usum0.z * pr0.z + usum0.w * pr0.w;
    float pd1 = usum1.x * pr1.x + usum1.y * pr1.y + usum1.z * pr1.z + usum1.w * pr1.w;

    // --- negative rows summed first (dot distributes over the sum) ---
    float4 ns0 = make_float4(0.f, 0.f, 0.f, 0.f);
    float4 ns1 = make_float4(0.f, 0.f, 0.f, 0.f);
    const int* nw0 = neg_w + b0 * NEG;
    const int* nw1 = neg_w + b1 * NEG;
    #pragma unroll
    for (int k = 0; k < NEG; ++k) {
        int i0 = __ldg(nw0 + k);
        int i1 = __ldg(nw1 + k);
        float4 v0 = ldg_pol(w_w + (size_t)i0 * 32 + lane, pol_stream);
        float4 v1 = ldg_pol(w_w + (size_t)i1 * 32 + lane, pol_stream);
        ns0.x += v0.x; ns0.y += v0.y; ns0.z += v0.z; ns0.w += v0.w;
        ns1.x += v1.x; ns1.y += v1.y; ns1.z += v1.z; ns1.w += v1.w;
    }
    float nd0 = usum0.x * ns0.x + usum0.y * ns0.y + usum0.z * ns0.z + usum0.w * ns0.w;
    float nd1 = usum1.x * ns1.x + usum1.y * ns1.y + usum1.z * ns1.z + usum1.w * ns1.w;

    // --- warp reduce all four dots together ---
    #pragma unroll
    for (int off = 16; off > 0; off >>= 1) {
        pd0 += __shfl_xor_sync(0xFFFFFFFFu, pd0, off);
        nd0 += __shfl_xor_sync(0xFFFFFFFFu, nd0, off);
        pd1 += __shfl_xor_sync(0xFFFFFFFFu, pd1, off);
        nd1 += __shfl_xor_sync(0xFFFFFFFFu, nd1, off);
    }

    __shared__ float s_part[WARPS_PER_BLOCK];
    if (lane == 0)
        s_part[warp] = log_sigmoid(pd0) + log_sigmoid(-nd0)
                     + log_sigmoid(pd1) + log_sigmoid(-nd1);
    __syncthreads();

    // --- featherweight epilogue: one double atomic per block + ticket ---
    if (threadIdx.x == 0) {
        float acc = 0.f;
        #pragma unroll
        for (int i = 0; i < WARPS_PER_BLOCK; ++i) acc += s_part[i];
        atomicAdd(&g_accum, (double)acc);   // order-insensitive in double
        __threadfence();                    // release before ticket
        unsigned int t = atomicAdd(&g_ticket, 1u);
        if (t == NUM_BLOCKS - 1) {
            __threadfence();                // acquire after last ticket
            double total = g_accum;
            out[0] = (float)(-total);       // loss = -(sum of logsigmoids)
            g_accum  = 0.0;                 // reset for next graph replay
            g_ticket = 0;
        }
    }
}

extern "C" void kernel_launch(void* const* d_in, const int* in_sizes, int n_in,
                              void* d_out, int out_size) {
    const int*    pos_u = (const int*)d_in[0];
    const int*    pos_w = (const int*)d_in[1];
    const int*    neg_w = (const int*)d_in[2];
    const float4* u_w   = (const float4*)d_in[3];
    const float4* w_w   = (const float4*)d_in[4];
    float* out = (float*)d_out;

    cbow_loss_fused<<<NUM_BLOCKS, THREADS>>>(pos_u, pos_w, neg_w, u_w, w_w, out);
}

// round 8
// speedup vs baseline: 1.2526x; 1.2526x over previous
#include <cuda_runtime.h>
#include <math.h>

// Problem constants (fixed by reference)
#define VOCAB 100000
#define DIM   128
#define BATCH 16384
#define CTX   10
#define NEG   5

#define WARPS_PER_BLOCK 8
#define THREADS (WARPS_PER_BLOCK * 32)
#define ELEMS_PER_WARP 2
#define NUM_BLOCKS (BATCH / (WARPS_PER_BLOCK * ELEMS_PER_WARP))   // 1024: single CTA wave

// Scratch (no cudaMalloc allowed)
__device__ double       g_accum  = 0.0;
__device__ unsigned int g_ticket = 0;

__device__ __forceinline__ float log_sigmoid(float x) {
    // stable: min(x,0) - log1p(exp(-|x|))
    return fminf(x, 0.0f) - log1pf(expf(-fabsf(x)));
}

// u-table: evict_last (larger unique miss stream; bias retention in L2).
__device__ __forceinline__ unsigned long long make_policy_keep() {
    unsigned long long pol;
    asm("createpolicy.fractional.L2::evict_last.b64 %0, 1.0;" : "=l"(pol));
    return pol;
}
__device__ __forceinline__ float4 ldg_pol(const float4* p, unsigned long long pol) {
    float4 v;
    asm("ld.global.nc.L2::cache_hint.v4.f32 {%0,%1,%2,%3}, [%4], %5;"
        : "=f"(v.x), "=f"(v.y), "=f"(v.z), "=f"(v.w)
        : "l"(p), "l"(pol));
    return v;
}

__global__ __launch_bounds__(THREADS)
void cbow_loss_fused(const int* __restrict__ pos_u,   // [B, CTX]
                     const int* __restrict__ pos_w,   // [B]
                     const int* __restrict__ neg_w,   // [B, NEG]
                     const float4* __restrict__ u_w,  // [VOCAB, 32] as float4
                     const float4* __restrict__ w_w,  // [VOCAB, 32] as float4
                     float* __restrict__ out)
{
    const int warp = threadIdx.x >> 5;
    const int lane = threadIdx.x & 31;
    const int b0 = (blockIdx.x * WARPS_PER_BLOCK + warp) * ELEMS_PER_WARP;

    const unsigned long long pol_keep = make_policy_keep();

    float ls = 0.0f;   // lane0 accumulates logsigmoid terms

    #pragma unroll
    for (int e = 0; e < ELEMS_PER_WARP; ++e) {
        const int b = b0 + e;

        // --- gather-sum context embeddings (u-table: keep) ---
        float4 usum = make_float4(0.f, 0.f, 0.f, 0.f);
        const int* pu = pos_u + b * CTX;
        #pragma unroll
        for (int c = 0; c < CTX; ++c) {
            int idx = __ldg(pu + c);                     // uniform across warp
            float4 v = ldg_pol(u_w + (size_t)idx * 32 + lane, pol_keep);
            usum.x += v.x; usum.y += v.y; usum.z += v.z; usum.w += v.w;
        }

        // --- positive target row (w-table: default policy; rows re-hit ~1.6x) ---
        int pidx = __ldg(pos_w + b);
        float4 p = __ldg(w_w + (size_t)pidx * 32 + lane);
        float pd = usum.x * p.x + usum.y * p.y + usum.z * p.z + usum.w * p.w;

        // --- negative rows summed first (dot distributes over the sum) ---
        float4 nsum = make_float4(0.f, 0.f, 0.f, 0.f);
        const int* nw = neg_w + b * NEG;
        #pragma unroll
        for (int k = 0; k < NEG; ++k) {
            int idx = __ldg(nw + k);
            float4 v = __ldg(w_w + (size_t)idx * 32 + lane);
            nsum.x += v.x; nsum.y += v.y; nsum.z += v.z; nsum.w += v.w;
        }
        float nd = usum.x * nsum.x + usum.y * nsum.y + usum.z * nsum.z + usum.w * nsum.w;

        // --- warp reduce both dots together ---
        #pragma unroll
        for (int off = 16; off > 0; off >>= 1) {
            pd += __shfl_xor_sync(0xFFFFFFFFu, pd, off);
            nd += __shfl_xor_sync(0xFFFFFFFFu, nd, off);
        }
        if (lane == 0)
            ls += log_sigmoid(pd) + log_sigmoid(-nd);
    }

    __shared__ float s_part[WARPS_PER_BLOCK];
    if (lane == 0)
        s_part[warp] = ls;
    __syncthreads();

    // --- featherweight epilogue: one double atomic per block + ticket ---
    if (threadIdx.x == 0) {
        float acc = 0.f;
        #pragma unroll
        for (int i = 0; i < WARPS_PER_BLOCK; ++i) acc += s_part[i];
        atomicAdd(&g_accum, (double)acc);   // order-insensitive in double
        __threadfence();                    // release before ticket
        unsigned int t = atomicAdd(&g_ticket, 1u);
        if (t == NUM_BLOCKS - 1) {
            __threadfence();                // acquire after last ticket
            double total = g_accum;
            out[0] = (float)(-total);       // loss = -(sum of logsigmoids)
            g_accum  = 0.0;                 // reset for next graph replay
            g_ticket = 0;
        }
    }
}

extern "C" void kernel_launch(void* const* d_in, const int* in_sizes, int n_in,
                              void* d_out, int out_size) {
    const int*    pos_u = (const int*)d_in[0];
    const int*    pos_w = (const int*)d_in[1];
    const int*    neg_w = (const int*)d_in[2];
    const float4* u_w   = (const float4*)d_in[3];
    const float4* w_w   = (const float4*)d_in[4];
    float* out = (float*)d_out;

    cbow_loss_fused<<<NUM_BLOCKS, THREADS>>>(pos_u, pos_w, neg_w, u_w, w_w, out);
}